// round 12
// baseline (speedup 1.0000x reference)
#include <cuda_runtime.h>
#include <cuda_bf16.h>

#define T_      512
#define B_      512
#define EMB_    32
#define HID_    32
#define G4_     128   // 4*HID
#define FF_     16
#define NCLS_   7
#define VOCAB_  1000

typedef unsigned long long u64;

#define L2E_   1.4426950408889634f

// Gate pre-activations PRE-SCALED at build time for the tanh identity:
//   sigmoid(x) = 0.5*tanh(0.5x) + 0.5  -> i, f, o rows scaled by 0.5
//   tanh(x)    = tanh.approx directly  -> g row unscaled

// ---------------- scratch (static device memory) ----------------------------
__device__ u64 g_tabIF[VOCAB_ * HID_];         // {0.5*a_i, 0.5*a_f} per (v,k)
__device__ u64 g_tabGO[VOCAB_ * HID_];         // {a_g, 0.5*a_o} per (v,k)
__device__ float g_hs[(size_t)T_ * B_ * HID_]; // 32 MB hidden states

// ---------------- fast math --------------------------------------------------
__device__ __forceinline__ float ex2f(float x) {
    float r; asm("ex2.approx.f32 %0, %1;" : "=f"(r) : "f"(x)); return r;
}
__device__ __forceinline__ float tanhap(float x) {
    float r; asm("tanh.approx.f32 %0, %1;" : "=f"(r) : "f"(x)); return r;
}
// sigmoid with pre-halved argument: sg(a) = 0.5*tanh(a) + 0.5,  a = 0.5*x
__device__ __forceinline__ float sigm_h(float a) {
    return fmaf(0.5f, tanhap(a), 0.5f);
}

// ---------------- packed f32x2 helpers ---------------------------------------
__device__ __forceinline__ u64 pack2(float lo, float hi) {
    u64 d; asm("mov.b64 %0, {%1, %2};" : "=l"(d) : "f"(lo), "f"(hi)); return d;
}
__device__ __forceinline__ void unpack2(u64 v, float& lo, float& hi) {
    asm("mov.b64 {%0, %1}, %2;" : "=f"(lo), "=f"(hi) : "l"(v));
}
__device__ __forceinline__ u64 ffma2(u64 a, u64 b, u64 c) {
    u64 d; asm("fma.rn.f32x2 %0, %1, %2, %3;" : "=l"(d) : "l"(a), "l"(b), "l"(c));
    return d;
}
__device__ __forceinline__ u64 fadd2(u64 a, u64 b) {
    u64 d; asm("add.rn.f32x2 %0, %1, %2;" : "=l"(d) : "l"(a), "l"(b)); return d;
}

// ---- token dtype sniff ------------------------------------------------------
__device__ __forceinline__ bool x_is_i64(const int* __restrict__ x32) {
    return (x32[1] | x32[3] | x32[5] | x32[7] | x32[9]) == 0;
}
__device__ __forceinline__ int get_tok(const int* __restrict__ x32,
                                       bool i64, int idx) {
    return x32[i64 ? (idx << 1) : idx];
}

// ---------------- K1: packed + half-scaled gate tables ----------------------
__global__ __launch_bounds__(128) void k_table4(
    const float* __restrict__ emb, const float* __restrict__ W_ih,
    const float* __restrict__ b_ih, const float* __restrict__ b_hh)
{
    __shared__ float Wsh[G4_ * 33];       // [row][e] padded
    __shared__ float bsh[G4_];
    __shared__ float esh[8][EMB_];

    const int tid = threadIdx.x;
    const int v0  = blockIdx.x * 8;

#pragma unroll
    for (int i = 0; i < 32; ++i) {
        const int idx = tid + i * 128;
        Wsh[(idx >> 5) * 33 + (idx & 31)] = W_ih[idx];
    }
    bsh[tid] = b_ih[tid] + b_hh[tid];
#pragma unroll
    for (int i = 0; i < 2; ++i) {
        const int idx = tid + i * 128;
        esh[idx >> 5][idx & 31] = emb[v0 * EMB_ + idx];
    }
    __syncthreads();

    const int gate = tid >> 5;            // 0=i 1=f 2=g 3=o
    const int k    = tid & 31;
    const int row  = gate * HID_ + k;
    const float bias = bsh[row];
    const float scale = (gate == 2) ? 1.0f : 0.5f;
    float* dstIF = reinterpret_cast<float*>(g_tabIF);
    float* dstGO = reinterpret_cast<float*>(g_tabGO);

#pragma unroll
    for (int v = 0; v < 8; ++v) {
        float acc = bias;
#pragma unroll
        for (int e = 0; e < EMB_; ++e)
            acc = fmaf(Wsh[row * 33 + e], esh[v][e], acc);
        acc *= scale;
        const int vv = v0 + v;
        if (gate < 2) dstIF[vv * 64 + k * 2 + gate]       = acc;
        else          dstGO[vv * 64 + k * 2 + (gate - 2)] = acc;
    }
}

// ---------------- K2: LSTM, LDS-broadcast {h,h} + MUFU tanh -----------------
// Warp per batch element. lane k owns h[k], c[k].
// h stored duplicated {h,h} in shared (double-buffered); matvec reads it as
// 16 uniform LDS.128 broadcasts -> no SHFL, no per-j packing MOVs.
__global__ __launch_bounds__(128) void k_lstm9(
    const int* __restrict__ x, const float* __restrict__ W_hh)
{
    __shared__ int tok_s[4][T_];                       // 8 KB
    __shared__ __align__(16) u64 h_sh2[4][2][HID_];    // 2 KB, {h,h} pairs

    const int tid  = threadIdx.x;
    const int wid  = tid >> 5;
    const int lane = tid & 31;
    const int b    = blockIdx.x * 4 + wid;
    const bool i64 = x_is_i64(x);

    for (int i = lane; i < T_; i += 32)
        tok_s[wid][i] = get_tok(x, i64, i * B_ + b);

    // packed recurrent weights, pre-scaled: i,f,o x0.5; g x1
    u64 Wif[HID_], Wgo[HID_];
#pragma unroll
    for (int j = 0; j < HID_; ++j) {
        Wif[j] = pack2(0.5f * W_hh[(0 * HID_ + lane) * HID_ + j],
                       0.5f * W_hh[(1 * HID_ + lane) * HID_ + j]);
        Wgo[j] = pack2(       W_hh[(2 * HID_ + lane) * HID_ + j],
                       0.5f * W_hh[(3 * HID_ + lane) * HID_ + j]);
    }

    h_sh2[wid][0][lane] = 0ull;            // {0,0}
    float c = 0.0f;
    int p = 0;
    __syncwarp();

    int tk = tok_s[wid][0];
    u64 xif_n = g_tabIF[tk * HID_ + lane];
    u64 xgo_n = g_tabGO[tk * HID_ + lane];

    for (int t = 0; t < T_; ++t) {
        u64 A0 = xif_n, A1 = 0ull;
        u64 G0 = xgo_n, G1 = 0ull;

        tk = tok_s[wid][(t + 1) & (T_ - 1)];
        xif_n = g_tabIF[tk * HID_ + lane];
        xgo_n = g_tabGO[tk * HID_ + lane];

        // 16 uniform LDS.128 broadcasts deliver {h_j,h_j} pairs
        const ulonglong2* hp = reinterpret_cast<const ulonglong2*>(h_sh2[wid][p]);
#pragma unroll
        for (int q = 0; q < HID_ / 2; ++q) {
            const ulonglong2 hh = hp[q];           // {h_2q,h_2q},{h_2q+1,h_2q+1}
            A0 = ffma2(Wif[2 * q + 0], hh.x, A0);
            G0 = ffma2(Wgo[2 * q + 0], hh.x, G0);
            A1 = ffma2(Wif[2 * q + 1], hh.y, A1);
            G1 = ffma2(Wgo[2 * q + 1], hh.y, G1);
        }
        const u64 aif = fadd2(A0, A1);
        const u64 ago = fadd2(G0, G1);

        float ai, af, ag, ao;
        unpack2(aif, ai, af);
        unpack2(ago, ag, ao);

        const float ig = sigm_h(ai);       // tanh.approx + fma
        const float fg = sigm_h(af);
        const float gg = tanhap(ag);       // single MUFU
        const float og = sigm_h(ao);
        c = fmaf(fg, c, ig * gg);
        const float h = og * tanhap(c);    // single MUFU on the chain

        h_sh2[wid][1 - p][lane] = pack2(h, h);
        g_hs[((size_t)t * B_ + b) * HID_ + lane] = h;  // coalesced 128B/warp
        __syncwarp();
        p ^= 1;
    }
}

// ---------------- K3: FF + logits, thread-per-row, f32x2 packed weights -----
__global__ __launch_bounds__(256) void k_ff5(
    const float* __restrict__ W1, const float* __restrict__ b1,
    const float* __restrict__ W2, const float* __restrict__ b2,
    float* __restrict__ out)
{
    __shared__ u64 w1p[HID_ * 8];         // [j][fp], 2 KB
    __shared__ u64 w2p[NCLS_ * 8];        // [cl][fp]
    __shared__ u64 b1p[8];
    __shared__ float b2s[NCLS_];

    const int tid = threadIdx.x;

    if (tid < HID_ * 8) {
        const int j  = tid >> 3;
        const int fp = tid & 7;
        w1p[j * 8 + fp] = pack2(W1[(2 * fp) * HID_ + j],
                                W1[(2 * fp + 1) * HID_ + j]);
    }
    if (tid < NCLS_ * 8) {
        const int cl = tid >> 3;
        const int fp = tid & 7;
        w2p[cl * 8 + fp] = pack2(W2[cl * FF_ + 2 * fp],
                                 W2[cl * FF_ + 2 * fp + 1]);
    }
    if (tid < 8)     b1p[tid] = pack2(b1[2 * tid], b1[2 * tid + 1]);
    if (tid < NCLS_) b2s[tid] = b2[tid];
    __syncthreads();

    const size_t r = (size_t)blockIdx.x * 256 + tid;   // flat row t*B+b

    float hv[HID_];
    const float4* hp = reinterpret_cast<const float4*>(&g_hs[r * HID_]);
#pragma unroll
    for (int q = 0; q < HID_ / 4; ++q) {
        const float4 v = hp[q];
        hv[q * 4 + 0] = v.x; hv[q * 4 + 1] = v.y;
        hv[q * 4 + 2] = v.z; hv[q * 4 + 3] = v.w;
    }

    u64 acc[8];
#pragma unroll
    for (int fp = 0; fp < 8; ++fp) acc[fp] = b1p[fp];
#pragma unroll
    for (int j = 0; j < HID_; ++j) {
        const u64 hh = pack2(hv[j], hv[j]);
#pragma unroll
        for (int fp = 0; fp < 8; ++fp)
            acc[fp] = ffma2(w1p[j * 8 + fp], hh, acc[fp]);
    }
#pragma unroll
    for (int fp = 0; fp < 8; ++fp) {
        float lo, hi;
        unpack2(acc[fp], lo, hi);
        acc[fp] = pack2(fmaxf(lo, 0.0f), fmaxf(hi, 0.0f));
    }

    float* orow = &out[r * NCLS_];
#pragma unroll
    for (int cl = 0; cl < NCLS_; ++cl) {
        u64 a2 = 0ull;
#pragma unroll
        for (int fp = 0; fp < 8; ++fp)
            a2 = ffma2(w2p[cl * 8 + fp], acc[fp], a2);
        float lo, hi;
        unpack2(a2, lo, hi);
        orow[cl] = b2s[cl] + lo + hi;
    }
}

// ---------------- K4: softmax over T, column-parallel, single global read ---
__global__ __launch_bounds__(256) void k_softmax5(float* __restrict__ out)
{
    __shared__ float red[8][32];
    const int tid   = threadIdx.x;
    const int cin   = tid & 31;
    const int chunk = tid >> 5;
    const int col   = blockIdx.x * 32 + cin;
    const int t0    = chunk * 64;

    float vv[64];
    float m = -1e30f;
#pragma unroll
    for (int i = 0; i < 64; ++i) {
        vv[i] = out[(size_t)(t0 + i) * 3584 + col];
        m = fmaxf(m, vv[i]);
    }
    red[chunk][cin] = m;
    __syncthreads();
#pragma unroll
    for (int q = 0; q < 8; ++q) m = fmaxf(m, red[q][cin]);
    __syncthreads();

    float s = 0.0f;
#pragma unroll
    for (int i = 0; i < 64; ++i) {
        vv[i] = ex2f(L2E_ * (vv[i] - m));
        s += vv[i];
    }
    red[chunk][cin] = s;
    __syncthreads();
    s = 0.0f;
#pragma unroll
    for (int q = 0; q < 8; ++q) s += red[q][cin];
    const float R = 1.0f / s;

#pragma unroll
    for (int i = 0; i < 64; ++i)
        out[(size_t)(t0 + i) * 3584 + col] = vv[i] * R;
}

// ---------------- launch: bind by size + infer W-pair orientation -----------
extern "C" void kernel_launch(void* const* d_in, const int* in_sizes, int n_in,
                              void* d_out, int out_size)
{
    const int*   x    = nullptr;
    const float* emb  = nullptr;
    const float* Wp0  = nullptr;
    const float* Wp1  = nullptr;
    const float* b_ih = nullptr;
    const float* b_hh = nullptr;
    const float* W1   = nullptr;
    const float* b1   = nullptr;
    const float* W2   = nullptr;
    const float* b2   = nullptr;
    int idx_W1 = -1, idx_Wp0 = -1;

    for (int i = 0; i < n_in; ++i) {
        const int s = in_sizes[i];
        const void* p = d_in[i];
        switch (s) {
            case T_ * B_:
            case 2 * T_ * B_:
                if (!x) x = (const int*)p;
                break;
            case VOCAB_ * EMB_:
                emb = (const float*)p; break;
            case G4_ * EMB_:
                if (!Wp0) { Wp0 = (const float*)p; idx_Wp0 = i; }
                else      { Wp1 = (const float*)p; }
                break;
            case G4_:
                if (!b_ih) b_ih = (const float*)p; else b_hh = (const float*)p;
                break;
            case FF_ * HID_:
                W1 = (const float*)p; idx_W1 = i; break;
            case FF_:
                b1 = (const float*)p; break;
            case NCLS_ * FF_:
                W2 = (const float*)p; break;
            case NCLS_:
                b2 = (const float*)p; break;
            default: break;
        }
    }

    const bool sorted_order = (idx_W1 >= 0 && idx_Wp0 >= 0 && idx_W1 < idx_Wp0);
    const float* W_ih = sorted_order ? Wp1 : Wp0;
    const float* W_hh = sorted_order ? Wp0 : Wp1;

    float* out = (float*)d_out;

    k_table4   <<<VOCAB_ / 8, 128>>>(emb, W_ih, b_ih, b_hh);
    k_lstm9    <<<B_ / 4, 128>>>(x, W_hh);
    k_ff5      <<<(T_ * B_) / 256, 256>>>(W1, b1, W2, b2, out);
    k_softmax5 <<<3584 / 32, 256>>>(out);
}